// round 7
// baseline (speedup 1.0000x reference)
#include <cuda_runtime.h>
#include <cuda_bf16.h>

// Problem constants
#define B_   2
#define INC_ 64
#define OUTC_ 128
#define NP_  8
#define D_   12
#define H_   48
#define W_   48
#define HW_   (H_*W_)        // 2304
#define DHW_  (D_*HW_)       // 27648
#define OFFC_ (3*NP_)        // 24
#define REDN_ (B_*DHW_)      // 55296
#define POSBLK_ 64
#define NBLK_MAIN_ (B_*D_*(HW_/POSBLK_))   // 864

// Scratch (device globals; no allocations allowed)
__device__ float g_offset[B_*OFFC_*DHW_];    // ~5.3 MB
__device__ float g_out[B_*OUTC_*DHW_];       // ~28.3 MB
__device__ float g_wt[INC_*NP_*OUTC_];       // w_conv -> [n][c][o]  (n-major)
__device__ float g_xt[B_*DHW_*INC_];         // x -> channel-last [b][dhw][c]
__device__ float g_part[NBLK_MAIN_*OUTC_];
__device__ float g_part2[NBLK_MAIN_*OUTC_];
__device__ float g_mean[OUTC_];
__device__ float g_rstd[OUTC_];

// _p_n(8): base=3, dep=2, row=1, mod=2
__device__ __constant__ float c_pnz[8] = {0,0,0,1,1,1,2,2};
__device__ __constant__ float c_pnx[8] = {0,0,0,0,0,0,1,1};
__device__ __constant__ float c_pny[8] = {0,1,2,0,1,2,0,1};

// ---------------- f32x2 helpers (FFMA2 path, fp32-exact) ----------------
typedef unsigned long long u64;

__device__ __forceinline__ void ffma2(u64 &d, u64 a, u64 b) {
    asm("fma.rn.f32x2 %0, %1, %2, %0;" : "+l"(d) : "l"(a), "l"(b));
}
__device__ __forceinline__ u64 dup2(float x) {
    u64 r; asm("mov.b64 %0, {%1, %1};" : "=l"(r) : "f"(x)); return r;
}
__device__ __forceinline__ u64 pack2(float lo, float hi) {
    u64 r; asm("mov.b64 %0, {%1, %2};" : "=l"(r) : "f"(lo), "f"(hi)); return r;
}
__device__ __forceinline__ float lo32(u64 v){ return __uint_as_float((unsigned int)v); }
__device__ __forceinline__ float hi32(u64 v){ return __uint_as_float((unsigned int)(v >> 32)); }

// ---------------------------------------------------------------------------
// Kernel PRE (merged): blocks [0,288)   = offset conv (R4 body)
//                      blocks [288,1152)= x transpose to channel-last
//                      blocks [1152,1408)= w_conv transpose to [n][c][o]
// 288 threads each; shared pool = union of the two users (50688 B static,
// same footprint that compiled & ran in R2/R4).
// ---------------------------------------------------------------------------
__global__ void __launch_bounds__(288) k_pre(
    const float* __restrict__ x,
    const float* __restrict__ w_p,
    const float* __restrict__ b_p,
    const float* __restrict__ w_conv)
{
    __shared__ float sp[12672];          // offset: x_s[7488] + w_s[5184]; xt: tile[64*65]
    const int blk = blockIdx.x;
    const int tid = threadIdx.x;

    if (blk < 288) {
        // ---------------- offset conv (exact R4 body) ----------------
        float* x_s = sp;                 // [8][3][6][52]
        float* w_s = sp + 7488;          // [8][27][24]
        const int hblk = blk % (H_/4);
        const int d = (blk / (H_/4)) % D_;
        const int b = blk / ((H_/4)*D_);
        const int h0 = hblk * 4;
        const int hh  = tid / 72;
        const int r   = tid % 72;
        const int ocg = r / 12;
        const int wq  = r % 12;

        u64 acc[2][4];
        {
            u64 p0 = pack2(__ldg(&b_p[ocg*4+0]), __ldg(&b_p[ocg*4+1]));
            u64 p1 = pack2(__ldg(&b_p[ocg*4+2]), __ldg(&b_p[ocg*4+3]));
            #pragma unroll
            for (int i = 0; i < 4; i++) { acc[0][i] = p0; acc[1][i] = p1; }
        }

        for (int cc = 0; cc < 8; cc++) {
            __syncthreads();
            for (int idx = tid; idx < 7488; idx += 288) {
                int wl = idx % 52; int t = idx / 52;
                int dh = t % 6; t /= 6;
                int dz = t % 3; int c = t / 3;
                int gd = d + dz - 1, gh = h0 + dh - 1, gw = wl - 1;
                float v = 0.f;
                if ((unsigned)gd < (unsigned)D_ && (unsigned)gh < (unsigned)H_ &&
                    (unsigned)gw < (unsigned)W_)
                    v = x[((b*INC_ + cc*8 + c)*D_ + gd)*HW_ + gh*W_ + gw];
                x_s[idx] = v;
            }
            for (int idx = tid; idx < 5184; idx += 288) {
                int k  = idx % 27;
                int oc = (idx / 27) % 24;
                int c  = idx / 648;
                w_s[c*648 + k*24 + oc] = w_p[(oc*INC_ + cc*8 + c)*27 + k];
            }
            __syncthreads();

            #pragma unroll 2
            for (int c = 0; c < 8; c++) {
                #pragma unroll
                for (int kz = 0; kz < 3; kz++)
                #pragma unroll
                for (int kx = 0; kx < 3; kx++) {
                    const float* xb = &x_s[((c*3 + kz)*6 + hh + kx)*52 + wq*4];
                    float4 xa = *reinterpret_cast<const float4*>(xb);
                    float2 xc = *reinterpret_cast<const float2*>(xb + 4);
                    u64 X[6] = { dup2(xa.x), dup2(xa.y), dup2(xa.z),
                                 dup2(xa.w), dup2(xc.x), dup2(xc.y) };
                    #pragma unroll
                    for (int ky = 0; ky < 3; ky++) {
                        ulonglong2 Wv = *reinterpret_cast<const ulonglong2*>(
                            &w_s[(c*27 + kz*9 + kx*3 + ky)*24 + ocg*4]);
                        #pragma unroll
                        for (int i = 0; i < 4; i++) {
                            ffma2(acc[0][i], Wv.x, X[ky + i]);
                            ffma2(acc[1][i], Wv.y, X[ky + i]);
                        }
                    }
                }
            }
        }

        const int h = h0 + hh;
        #pragma unroll
        for (int p = 0; p < 2; p++) {
            float4 vl = make_float4(lo32(acc[p][0]), lo32(acc[p][1]),
                                    lo32(acc[p][2]), lo32(acc[p][3]));
            float4 vh = make_float4(hi32(acc[p][0]), hi32(acc[p][1]),
                                    hi32(acc[p][2]), hi32(acc[p][3]));
            int oc0 = ocg*4 + p*2;
            *reinterpret_cast<float4*>(
                &g_offset[((b*OFFC_ + oc0    )*D_ + d)*HW_ + h*W_ + wq*4]) = vl;
            *reinterpret_cast<float4*>(
                &g_offset[((b*OFFC_ + oc0 + 1)*D_ + d)*HW_ + h*W_ + wq*4]) = vh;
        }
    } else if (blk < 288 + 864) {
        // ---------------- x transpose (channel-last) ----------------
        float* tile = sp;                // [64][65]
        const int bid = blk - 288;
        const int b = bid / (DHW_/64);
        const int p0 = (bid % (DHW_/64)) * 64;
        for (int idx = tid; idx < 4096; idx += 288) {
            int c = idx >> 6, p = idx & 63;
            tile[c*65 + p] = x[(b*INC_ + c)*DHW_ + p0 + p];
        }
        __syncthreads();
        for (int idx = tid; idx < 4096; idx += 288) {
            int p = idx >> 6, c = idx & 63;
            g_xt[(b*DHW_ + p0 + p)*INC_ + c] = tile[c*65 + p];
        }
    } else {
        // ---------------- w_conv transpose ----------------
        if (tid < 256) {
            int idx = (blk - 1152) * 256 + tid;     // 65536 total
            int nn = idx & 7;
            int c  = (idx >> 3) & 63;
            int o  = idx >> 9;
            g_wt[(nn*INC_ + c)*OUTC_ + o] = w_conv[idx];
        }
    }
}

// ---------------------------------------------------------------------------
// Kernel 2: fused deformable gather + 1x1xN conv (FFMA2) + BN partials.
// 64-pos blocks (864 total), 256 threads, 65.8KB dyn SMEM -> 3 blocks/SM.
//   gather per nn: warp wid covers pos p = wid*8..wid*8+7
//   GEMM  per nn : warp = ocg (16 oc), lanes = pos (lane + 32j, j<2)
// ---------------------------------------------------------------------------
__global__ void __launch_bounds__(256, 3) k_main()
{
    extern __shared__ unsigned char smraw[];
    int*   idx_s = (int*)smraw;                          // [512*4]  8KB
    float* gwt_s = (float*)(smraw + 8192);               // [512*4]  8KB
    float* xoff  = (float*)(smraw + 16384);              // [64][65] 16.64KB
    float* wt_s  = (float*)(smraw + 33024);              // [64][128] 32KB

    const int bid = blockIdx.x;
    const int p0   = (bid % (HW_/POSBLK_)) * POSBLK_;
    const int slab = bid / (HW_/POSBLK_);
    const int d = slab % D_;
    const int b = slab / D_;
    const int tid = threadIdx.x;
    const int lane = tid & 31;
    const int wid  = tid >> 5;

    // ---- setup: corner indices + trilinear weights for 512 (pos,n) ----
    const int bD = b * DHW_;
    #pragma unroll
    for (int i = 0; i < 2; i++) {
        const int q = tid + 256*i;          // q = n*64 + p
        const int p = q & 63;
        const int n = q >> 6;
        const int pos = p0 + p;
        const int h = pos / W_;
        const int w = pos % W_;
        const int off_base = (b*OFFC_*D_ + d)*HW_ + pos;
        const float oz = g_offset[off_base + (n       )*DHW_];
        const float ox = g_offset[off_base + (NP_  + n)*DHW_];
        const float oy = g_offset[off_base + (2*NP_+ n)*DHW_];

        const float pz = oz + (float)d + c_pnz[n];
        const float px = ox + (float)h + c_pnx[n];
        const float py = oy + (float)w + c_pny[n];

        const float fz = floorf(pz), fx = floorf(px), fy = floorf(py);
        const float z0f = fminf(fmaxf(fz,       0.f), (float)(D_-1));
        const float z1f = fminf(fmaxf(fz + 1.f, 0.f), (float)(D_-1));
        const float x0f = fminf(fmaxf(fx,       0.f), (float)(H_-1));
        const float x1f = fminf(fmaxf(fx + 1.f, 0.f), (float)(H_-1));
        const float y0f = fminf(fmaxf(fy,       0.f), (float)(W_-1));
        const float y1f = fminf(fmaxf(fy + 1.f, 0.f), (float)(W_-1));
        const float pzc = fminf(fmaxf(pz, 0.f), (float)(D_-1));
        const float pxc = fminf(fmaxf(px, 0.f), (float)(H_-1));
        const float pyc = fminf(fmaxf(py, 0.f), (float)(W_-1));

        const float az = 1.f + (z0f - pzc), bz = 1.f - (z1f - pzc);
        const float ax = 1.f + (x0f - pxc), bx = 1.f - (x1f - pxc);
        const float ay = 1.f + (y0f - pyc), by = 1.f - (y1f - pyc);

        const int z0 = (int)z0f, z1 = (int)z1f;
        const int x0 = (int)x0f, x1 = (int)x1f;
        const int y0 = (int)y0f, y1 = (int)y1f;

        idx_s[q*4+0] = (bD + z0*HW_ + x0*W_ + y0)*INC_;
        idx_s[q*4+1] = (bD + z1*HW_ + x1*W_ + y1)*INC_;
        idx_s[q*4+2] = (bD + z0*HW_ + x1*W_ + y0)*INC_;
        idx_s[q*4+3] = (bD + z1*HW_ + x0*W_ + y1)*INC_;
        gwt_s[q*4+0] = az*ax*ay;
        gwt_s[q*4+1] = bz*bx*by;
        gwt_s[q*4+2] = az*bx*ay;
        gwt_s[q*4+3] = bz*ax*by;
    }

    u64 acc[8][2];
    #pragma unroll
    for (int pr = 0; pr < 8; pr++) { acc[pr][0] = 0ull; acc[pr][1] = 0ull; }

    const int f    = lane & 15;     // channel-quad
    const int half = lane >> 4;     // corner pair selector

    for (int nn = 0; nn < 8; nn++) {
        __syncthreads();            // protect wt_s / xoff reuse
        // stage weights for this n: g_wt[nn*64 .. ][128]
        {
            const float4* src = reinterpret_cast<const float4*>(g_wt + nn*8192);
            float4* dst = reinterpret_cast<float4*>(wt_s);
            #pragma unroll
            for (int j = 0; j < 8; j++) dst[tid + 256*j] = __ldg(&src[tid + 256*j]);
        }
        // gather: warp wid covers pos p = wid*8 .. wid*8+7
        #pragma unroll
        for (int pp = 0; pp < 8; pp++) {
            const int p = wid*8 + pp;
            const int q4 = ((nn << 6) + p) << 2;
            const int   i0 = idx_s[q4 + half];
            const float g0 = gwt_s[q4 + half];
            const int   i1 = idx_s[q4 + half + 2];
            const float g1 = gwt_s[q4 + half + 2];
            const float4 v0 = __ldg((const float4*)(g_xt + i0 + 4*f));
            const float4 v1 = __ldg((const float4*)(g_xt + i1 + 4*f));
            float4 rv;
            rv.x = g0*v0.x + g1*v1.x;
            rv.y = g0*v0.y + g1*v1.y;
            rv.z = g0*v0.z + g1*v1.z;
            rv.w = g0*v0.w + g1*v1.w;
            rv.x += __shfl_xor_sync(0xffffffffu, rv.x, 16);
            rv.y += __shfl_xor_sync(0xffffffffu, rv.y, 16);
            rv.z += __shfl_xor_sync(0xffffffffu, rv.z, 16);
            rv.w += __shfl_xor_sync(0xffffffffu, rv.w, 16);
            if (half == 0) {
                // scalar stores: stride-65 rows are only 4B-aligned (no STS.128)
                float* rowp = &xoff[p*65 + 4*f];
                rowp[0] = rv.x;
                rowp[1] = rv.y;
                rowp[2] = rv.z;
                rowp[3] = rv.w;
            }
        }
        __syncthreads();

        // GEMM: warp = ocg, 16 oc; lanes = pos (lane + 32j, j<2)
        const int ocg = wid;
        #pragma unroll 4
        for (int k = 0; k < 64; k++) {
            const float x0 = xoff[(lane      )*65 + k];
            const float x1 = xoff[(lane + 32 )*65 + k];
            const ulonglong2 wa = *reinterpret_cast<const ulonglong2*>(&wt_s[k*128 + ocg*16     ]);
            const ulonglong2 wb = *reinterpret_cast<const ulonglong2*>(&wt_s[k*128 + ocg*16 + 4 ]);
            const ulonglong2 wc = *reinterpret_cast<const ulonglong2*>(&wt_s[k*128 + ocg*16 + 8 ]);
            const ulonglong2 wd = *reinterpret_cast<const ulonglong2*>(&wt_s[k*128 + ocg*16 + 12]);
            const u64 X0 = dup2(x0), X1 = dup2(x1);
            ffma2(acc[0][0], wa.x, X0); ffma2(acc[0][1], wa.x, X1);
            ffma2(acc[1][0], wa.y, X0); ffma2(acc[1][1], wa.y, X1);
            ffma2(acc[2][0], wb.x, X0); ffma2(acc[2][1], wb.x, X1);
            ffma2(acc[3][0], wb.y, X0); ffma2(acc[3][1], wb.y, X1);
            ffma2(acc[4][0], wc.x, X0); ffma2(acc[4][1], wc.x, X1);
            ffma2(acc[5][0], wc.y, X0); ffma2(acc[5][1], wc.y, X1);
            ffma2(acc[6][0], wd.x, X0); ffma2(acc[6][1], wd.x, X1);
            ffma2(acc[7][0], wd.y, X0); ffma2(acc[7][1], wd.y, X1);
        }
    }

    // ---- epilogue: store conv out (coalesced) + warp-reduced BN partials ----
    const int ocg = wid;
    #pragma unroll
    for (int pr = 0; pr < 8; pr++) {
        const int oc0 = ocg*16 + pr*2;
        float sl = 0.f, sl2 = 0.f, sh = 0.f, sh2 = 0.f;
        #pragma unroll
        for (int j = 0; j < 2; j++) {
            const int pos = p0 + lane + 32*j;
            const float vl = lo32(acc[pr][j]);
            const float vh = hi32(acc[pr][j]);
            g_out[((b*OUTC_ + oc0    )*D_ + d)*HW_ + pos] = vl;
            g_out[((b*OUTC_ + oc0 + 1)*D_ + d)*HW_ + pos] = vh;
            sl += vl; sl2 += vl*vl;
            sh += vh; sh2 += vh*vh;
        }
        #pragma unroll
        for (int st = 16; st > 0; st >>= 1) {
            sl  += __shfl_xor_sync(0xffffffffu, sl,  st);
            sl2 += __shfl_xor_sync(0xffffffffu, sl2, st);
            sh  += __shfl_xor_sync(0xffffffffu, sh,  st);
            sh2 += __shfl_xor_sync(0xffffffffu, sh2, st);
        }
        if (lane == 0) {
            g_part [bid*OUTC_ + oc0    ] = sl;
            g_part2[bid*OUTC_ + oc0    ] = sl2;
            g_part [bid*OUTC_ + oc0 + 1] = sh;
            g_part2[bid*OUTC_ + oc0 + 1] = sh2;
        }
    }
}

// ---------------------------------------------------------------------------
// Kernel 3a: reduce block partials -> mean/rstd (deterministic)
// ---------------------------------------------------------------------------
__global__ void __launch_bounds__(128) k_stats_final()
{
    const int oc = blockIdx.x;
    const int t  = threadIdx.x;
    float S = 0.f, S2 = 0.f;
    for (int i = t; i < NBLK_MAIN_; i += 128) {
        S  += g_part [i*OUTC_ + oc];
        S2 += g_part2[i*OUTC_ + oc];
    }
    __shared__ float sh[128], sh2[128];
    sh[t] = S; sh2[t] = S2;
    __syncthreads();
    for (int st = 64; st > 0; st >>= 1) {
        if (t < st) { sh[t] += sh[t + st]; sh2[t] += sh2[t + st]; }
        __syncthreads();
    }
    if (t == 0) {
        float mean = sh[0] / (float)REDN_;
        float var  = sh2[0] / (float)REDN_ - mean*mean;
        g_mean[oc] = mean;
        g_rstd[oc] = rsqrtf(var + 1e-5f);
    }
}

// ---------------------------------------------------------------------------
// Kernel 3b: BN affine + SiLU -> d_out
// ---------------------------------------------------------------------------
__global__ void __launch_bounds__(256) k_bn_silu(
    const float* __restrict__ gamma,
    const float* __restrict__ beta,
    float* __restrict__ out)
{
    const int idx = blockIdx.x * 256 + threadIdx.x;
    const int o = (idx / DHW_) & (OUTC_ - 1);
    const float v = g_out[idx];
    const float y = (v - g_mean[o]) * g_rstd[o] * __ldg(&gamma[o]) + __ldg(&beta[o]);
    out[idx] = y / (1.f + __expf(-y));
}

// ---------------------------------------------------------------------------
extern "C" void kernel_launch(void* const* d_in, const int* in_sizes, int n_in,
                              void* d_out, int out_size)
{
    const float* x      = (const float*)d_in[0];
    const float* w_p    = (const float*)d_in[1];
    const float* b_p    = (const float*)d_in[2];
    const float* w_conv = (const float*)d_in[3];
    const float* gamma  = (const float*)d_in[4];
    const float* beta   = (const float*)d_in[5];
    float* out = (float*)d_out;

    cudaFuncSetAttribute(k_main, cudaFuncAttributeMaxDynamicSharedMemorySize, 65792);

    k_pre<<<288 + 864 + 256, 288>>>(x, w_p, b_p, w_conv);      // merged prep
    k_main<<<NBLK_MAIN_, 256, 65792>>>();                      // 864 blocks
    k_stats_final<<<OUTC_, 128>>>();                           // 128 blocks
    k_bn_silu<<<B_*OUTC_*DHW_/256, 256>>>(gamma, beta, out);   // 27648 blocks
}

// round 8
// speedup vs baseline: 1.1515x; 1.1515x over previous
#include <cuda_runtime.h>
#include <cuda_bf16.h>

// Problem constants
#define B_   2
#define INC_ 64
#define OUTC_ 128
#define NP_  8
#define D_   12
#define H_   48
#define W_   48
#define HW_   (H_*W_)        // 2304
#define DHW_  (D_*HW_)       // 27648
#define OFFC_ (3*NP_)        // 24
#define REDN_ (B_*DHW_)      // 55296
#define POSBLK_ 128
#define NBLK_MAIN_ (B_*D_*(HW_/POSBLK_))   // 432

// Scratch (device globals; no allocations allowed)
__device__ float g_offset[B_*OFFC_*DHW_];    // ~5.3 MB
__device__ float g_out[B_*OUTC_*DHW_];       // ~28.3 MB
__device__ float g_wt[INC_*NP_*OUTC_];       // w_conv -> [n][c][o]  (n-major)
__device__ float g_xt[B_*DHW_*INC_];         // x -> channel-last [b][dhw][c]
__device__ float g_part[NBLK_MAIN_*OUTC_];
__device__ float g_part2[NBLK_MAIN_*OUTC_];
__device__ float g_mean[OUTC_];
__device__ float g_rstd[OUTC_];

// _p_n(8): base=3, dep=2, row=1, mod=2
__device__ __constant__ float c_pnz[8] = {0,0,0,1,1,1,2,2};
__device__ __constant__ float c_pnx[8] = {0,0,0,0,0,0,1,1};
__device__ __constant__ float c_pny[8] = {0,1,2,0,1,2,0,1};

// ---------------- f32x2 helpers (FFMA2 path, fp32-exact) ----------------
typedef unsigned long long u64;

__device__ __forceinline__ void ffma2(u64 &d, u64 a, u64 b) {
    asm("fma.rn.f32x2 %0, %1, %2, %0;" : "+l"(d) : "l"(a), "l"(b));
}
__device__ __forceinline__ u64 dup2(float x) {
    u64 r; asm("mov.b64 %0, {%1, %1};" : "=l"(r) : "f"(x)); return r;
}
__device__ __forceinline__ u64 pack2(float lo, float hi) {
    u64 r; asm("mov.b64 %0, {%1, %2};" : "=l"(r) : "f"(lo), "f"(hi)); return r;
}
__device__ __forceinline__ float lo32(u64 v){ return __uint_as_float((unsigned int)v); }
__device__ __forceinline__ float hi32(u64 v){ return __uint_as_float((unsigned int)(v >> 32)); }

// ---------------------------------------------------------------------------
// Kernel 0a: transpose w_conv [o][c][n] -> g_wt [n][c][o]  (n-major K order)
// ---------------------------------------------------------------------------
__global__ void k_wt(const float* __restrict__ w_conv) {
    int idx = blockIdx.x * 256 + threadIdx.x;      // 65536 total
    int nn = idx & 7;
    int c  = (idx >> 3) & 63;
    int o  = idx >> 9;
    g_wt[(nn*INC_ + c)*OUTC_ + o] = w_conv[idx];
}

// ---------------------------------------------------------------------------
// Kernel 0b: transpose x [b][c][dhw] -> g_xt [b][dhw][c] (channel-last)
// ---------------------------------------------------------------------------
__global__ void __launch_bounds__(256) k_xt(const float* __restrict__ x) {
    __shared__ float tile[64][65];
    const int bid = blockIdx.x;                 // 864 blocks
    const int b = bid / (DHW_/64);
    const int p0 = (bid % (DHW_/64)) * 64;
    const int tid = threadIdx.x;
    for (int idx = tid; idx < 4096; idx += 256) {
        int c = idx >> 6, p = idx & 63;
        tile[c][p] = x[(b*INC_ + c)*DHW_ + p0 + p];
    }
    __syncthreads();
    for (int idx = tid; idx < 4096; idx += 256) {
        int p = idx >> 6, c = idx & 63;
        g_xt[(b*DHW_ + p0 + p)*INC_ + c] = tile[c][p];
    }
}

// ---------------------------------------------------------------------------
// Kernel 1: offset conv (3x3x3, pad 1), FFMA2, spatial 576 blocks (h-pairs),
// NO split-K. 288 threads: hh=tid/144, ocg=(tid%144)/24 (4 oc), wq=tid%24 (2 w).
// 40.7 KB SMEM -> ~4 blocks/SM; grid 576 fills ~35 warps/SM.
// ---------------------------------------------------------------------------
__global__ void __launch_bounds__(288) k_offset_conv(
    const float* __restrict__ x,
    const float* __restrict__ w_p,
    const float* __restrict__ b_p)
{
    __shared__ float x_s[8*3*4*52];     // 4992 floats: [c8][dz3][dh4][w52]
    __shared__ float w_s[8*27*24];      // 5184 floats: [c8][k27][oc24]

    const int bid = blockIdx.x;         // 576 spatial blocks
    const int h0  = (bid % (H_/2)) * 2;
    const int d   = (bid / (H_/2)) % D_;
    const int b   = bid / ((H_/2)*D_);
    const int tid = threadIdx.x;
    const int hh  = tid / 144;          // 0..1
    const int r   = tid % 144;
    const int ocg = r / 24;             // 0..5  (4 oc each)
    const int wq  = r % 24;             // 0..23 (2 w each)
    const int w0  = wq * 2;

    u64 acc[2][2];
    {
        u64 p0 = pack2(__ldg(&b_p[ocg*4+0]), __ldg(&b_p[ocg*4+1]));
        u64 p1 = pack2(__ldg(&b_p[ocg*4+2]), __ldg(&b_p[ocg*4+3]));
        acc[0][0] = p0; acc[0][1] = p0;
        acc[1][0] = p1; acc[1][1] = p1;
    }

    for (int cc = 0; cc < 8; cc++) {
        __syncthreads();
        // stage x tile: [c8][dz3][dh4][w52], zero-padded
        for (int idx = tid; idx < 4992; idx += 288) {
            int wl = idx % 52; int t = idx / 52;
            int dh = t % 4; t /= 4;
            int dz = t % 3; int c = t / 3;
            int gd = d + dz - 1, gh = h0 + dh - 1, gw = wl - 1;
            float v = 0.f;
            if ((unsigned)gd < (unsigned)D_ && (unsigned)gh < (unsigned)H_ &&
                (unsigned)gw < (unsigned)W_)
                v = x[((b*INC_ + cc*8 + c)*D_ + gd)*HW_ + gh*W_ + gw];
            x_s[idx] = v;
        }
        // stage weights [c][k][oc]
        for (int idx = tid; idx < 5184; idx += 288) {
            int k  = idx % 27;
            int oc = (idx / 27) % 24;
            int c  = idx / 648;
            w_s[c*648 + k*24 + oc] = w_p[(oc*INC_ + cc*8 + c)*27 + k];
        }
        __syncthreads();

        #pragma unroll 2
        for (int c = 0; c < 8; c++) {
            #pragma unroll
            for (int kz = 0; kz < 3; kz++)
            #pragma unroll
            for (int kx = 0; kx < 3; kx++) {
                const float* xb = &x_s[((c*3 + kz)*4 + hh + kx)*52 + w0];
                float2 xa = *reinterpret_cast<const float2*>(xb);
                float2 xc = *reinterpret_cast<const float2*>(xb + 2);
                u64 X[4] = { dup2(xa.x), dup2(xa.y), dup2(xc.x), dup2(xc.y) };
                #pragma unroll
                for (int ky = 0; ky < 3; ky++) {
                    ulonglong2 Wv = *reinterpret_cast<const ulonglong2*>(
                        &w_s[(c*27 + kz*9 + kx*3 + ky)*24 + ocg*4]);
                    ffma2(acc[0][0], Wv.x, X[ky    ]);
                    ffma2(acc[0][1], Wv.x, X[ky + 1]);
                    ffma2(acc[1][0], Wv.y, X[ky    ]);
                    ffma2(acc[1][1], Wv.y, X[ky + 1]);
                }
            }
        }
    }

    const int h = h0 + hh;
    #pragma unroll
    for (int p = 0; p < 2; p++) {
        const int oc0 = ocg*4 + p*2;
        float2 v0 = make_float2(lo32(acc[p][0]), lo32(acc[p][1]));
        float2 v1 = make_float2(hi32(acc[p][0]), hi32(acc[p][1]));
        *reinterpret_cast<float2*>(
            &g_offset[((b*OFFC_ + oc0    )*D_ + d)*HW_ + h*W_ + w0]) = v0;
        *reinterpret_cast<float2*>(
            &g_offset[((b*OFFC_ + oc0 + 1)*D_ + d)*HW_ + h*W_ + w0]) = v1;
    }
}

// ---------------------------------------------------------------------------
// Kernel 2: fused deformable gather + 1x1xN conv (FFMA2) + BN partials.
// EXACT R4 version (proven 206.8us).
// ---------------------------------------------------------------------------
__global__ void __launch_bounds__(256) k_main()
{
    extern __shared__ unsigned char smraw[];
    int*   idx_s = (int*)smraw;                          // [1024*4]
    float* gwt_s = (float*)(smraw + 16384);              // [1024*4]
    float* xoff  = (float*)(smraw + 32768);              // [128][65]
    float* wt_s  = (float*)(smraw + 32768 + 33280);      // [64][128]

    const int bid = blockIdx.x;
    const int p0   = (bid % (HW_/POSBLK_)) * POSBLK_;
    const int slab = bid / (HW_/POSBLK_);
    const int d = slab % D_;
    const int b = slab / D_;
    const int tid = threadIdx.x;
    const int lane = tid & 31;
    const int wid  = tid >> 5;

    const int bD = b * DHW_;
    #pragma unroll
    for (int i = 0; i < 4; i++) {
        const int q = tid + 256*i;          // q = n*128 + p
        const int p = q & 127;
        const int n = q >> 7;
        const int pos = p0 + p;
        const int h = pos / W_;
        const int w = pos % W_;
        const int off_base = (b*OFFC_*D_ + d)*HW_ + pos;
        const float oz = g_offset[off_base + (n       )*DHW_];
        const float ox = g_offset[off_base + (NP_  + n)*DHW_];
        const float oy = g_offset[off_base + (2*NP_+ n)*DHW_];

        const float pz = oz + (float)d + c_pnz[n];
        const float px = ox + (float)h + c_pnx[n];
        const float py = oy + (float)w + c_pny[n];

        const float fz = floorf(pz), fx = floorf(px), fy = floorf(py);
        const float z0f = fminf(fmaxf(fz,       0.f), (float)(D_-1));
        const float z1f = fminf(fmaxf(fz + 1.f, 0.f), (float)(D_-1));
        const float x0f = fminf(fmaxf(fx,       0.f), (float)(H_-1));
        const float x1f = fminf(fmaxf(fx + 1.f, 0.f), (float)(H_-1));
        const float y0f = fminf(fmaxf(fy,       0.f), (float)(W_-1));
        const float y1f = fminf(fmaxf(fy + 1.f, 0.f), (float)(W_-1));
        const float pzc = fminf(fmaxf(pz, 0.f), (float)(D_-1));
        const float pxc = fminf(fmaxf(px, 0.f), (float)(H_-1));
        const float pyc = fminf(fmaxf(py, 0.f), (float)(W_-1));

        const float az = 1.f + (z0f - pzc), bz = 1.f - (z1f - pzc);
        const float ax = 1.f + (x0f - pxc), bx = 1.f - (x1f - pxc);
        const float ay = 1.f + (y0f - pyc), by = 1.f - (y1f - pyc);

        const int z0 = (int)z0f, z1 = (int)z1f;
        const int x0 = (int)x0f, x1 = (int)x1f;
        const int y0 = (int)y0f, y1 = (int)y1f;

        idx_s[q*4+0] = (bD + z0*HW_ + x0*W_ + y0)*INC_;
        idx_s[q*4+1] = (bD + z1*HW_ + x1*W_ + y1)*INC_;
        idx_s[q*4+2] = (bD + z0*HW_ + x1*W_ + y0)*INC_;
        idx_s[q*4+3] = (bD + z1*HW_ + x0*W_ + y1)*INC_;
        gwt_s[q*4+0] = az*ax*ay;
        gwt_s[q*4+1] = bz*bx*by;
        gwt_s[q*4+2] = az*bx*ay;
        gwt_s[q*4+3] = bz*ax*by;
    }

    u64 acc[8][4];
    #pragma unroll
    for (int pr = 0; pr < 8; pr++)
        #pragma unroll
        for (int j = 0; j < 4; j++) acc[pr][j] = 0ull;

    const int f    = lane & 15;     // channel-quad
    const int half = lane >> 4;     // corner pair selector

    for (int nn = 0; nn < 8; nn++) {
        __syncthreads();
        {
            const float4* src = reinterpret_cast<const float4*>(g_wt + nn*8192);
            float4* dst = reinterpret_cast<float4*>(wt_s);
            #pragma unroll
            for (int j = 0; j < 8; j++) dst[tid + 256*j] = __ldg(&src[tid + 256*j]);
        }
        #pragma unroll 2
        for (int pp = 0; pp < 16; pp++) {
            const int p = wid*16 + pp;
            const int q4 = ((nn << 7) + p) << 2;
            const int   i0 = idx_s[q4 + half];
            const float g0 = gwt_s[q4 + half];
            const int   i1 = idx_s[q4 + half + 2];
            const float g1 = gwt_s[q4 + half + 2];
            const float4 v0 = __ldg((const float4*)(g_xt + i0 + 4*f));
            const float4 v1 = __ldg((const float4*)(g_xt + i1 + 4*f));
            float4 rv;
            rv.x = g0*v0.x + g1*v1.x;
            rv.y = g0*v0.y + g1*v1.y;
            rv.z = g0*v0.z + g1*v1.z;
            rv.w = g0*v0.w + g1*v1.w;
            rv.x += __shfl_xor_sync(0xffffffffu, rv.x, 16);
            rv.y += __shfl_xor_sync(0xffffffffu, rv.y, 16);
            rv.z += __shfl_xor_sync(0xffffffffu, rv.z, 16);
            rv.w += __shfl_xor_sync(0xffffffffu, rv.w, 16);
            if (half == 0) {
                float* rowp = &xoff[p*65 + 4*f];
                rowp[0] = rv.x;
                rowp[1] = rv.y;
                rowp[2] = rv.z;
                rowp[3] = rv.w;
            }
        }
        __syncthreads();

        const int ocg = wid;
        #pragma unroll 4
        for (int k = 0; k < 64; k++) {
            const float x0 = xoff[(lane      )*65 + k];
            const float x1 = xoff[(lane + 32 )*65 + k];
            const float x2 = xoff[(lane + 64 )*65 + k];
            const float x3 = xoff[(lane + 96 )*65 + k];
            const ulonglong2 wa = *reinterpret_cast<const ulonglong2*>(&wt_s[k*128 + ocg*16     ]);
            const ulonglong2 wb = *reinterpret_cast<const ulonglong2*>(&wt_s[k*128 + ocg*16 + 4 ]);
            const ulonglong2 wc = *reinterpret_cast<const ulonglong2*>(&wt_s[k*128 + ocg*16 + 8 ]);
            const ulonglong2 wd = *reinterpret_cast<const ulonglong2*>(&wt_s[k*128 + ocg*16 + 12]);
            const u64 X0 = dup2(x0), X1 = dup2(x1), X2 = dup2(x2), X3 = dup2(x3);
            ffma2(acc[0][0], wa.x, X0); ffma2(acc[0][1], wa.x, X1);
            ffma2(acc[0][2], wa.x, X2); ffma2(acc[0][3], wa.x, X3);
            ffma2(acc[1][0], wa.y, X0); ffma2(acc[1][1], wa.y, X1);
            ffma2(acc[1][2], wa.y, X2); ffma2(acc[1][3], wa.y, X3);
            ffma2(acc[2][0], wb.x, X0); ffma2(acc[2][1], wb.x, X1);
            ffma2(acc[2][2], wb.x, X2); ffma2(acc[2][3], wb.x, X3);
            ffma2(acc[3][0], wb.y, X0); ffma2(acc[3][1], wb.y, X1);
            ffma2(acc[3][2], wb.y, X2); ffma2(acc[3][3], wb.y, X3);
            ffma2(acc[4][0], wc.x, X0); ffma2(acc[4][1], wc.x, X1);
            ffma2(acc[4][2], wc.x, X2); ffma2(acc[4][3], wc.x, X3);
            ffma2(acc[5][0], wc.y, X0); ffma2(acc[5][1], wc.y, X1);
            ffma2(acc[5][2], wc.y, X2); ffma2(acc[5][3], wc.y, X3);
            ffma2(acc[6][0], wd.x, X0); ffma2(acc[6][1], wd.x, X1);
            ffma2(acc[6][2], wd.x, X2); ffma2(acc[6][3], wd.x, X3);
            ffma2(acc[7][0], wd.y, X0); ffma2(acc[7][1], wd.y, X1);
            ffma2(acc[7][2], wd.y, X2); ffma2(acc[7][3], wd.y, X3);
        }
    }

    const int ocg = wid;
    #pragma unroll
    for (int pr = 0; pr < 8; pr++) {
        const int oc0 = ocg*16 + pr*2;
        float sl = 0.f, sl2 = 0.f, sh = 0.f, sh2 = 0.f;
        #pragma unroll
        for (int j = 0; j < 4; j++) {
            const int pos = p0 + lane + 32*j;
            const float vl = lo32(acc[pr][j]);
            const float vh = hi32(acc[pr][j]);
            g_out[((b*OUTC_ + oc0    )*D_ + d)*HW_ + pos] = vl;
            g_out[((b*OUTC_ + oc0 + 1)*D_ + d)*HW_ + pos] = vh;
            sl += vl; sl2 += vl*vl;
            sh += vh; sh2 += vh*vh;
        }
        #pragma unroll
        for (int st = 16; st > 0; st >>= 1) {
            sl  += __shfl_xor_sync(0xffffffffu, sl,  st);
            sl2 += __shfl_xor_sync(0xffffffffu, sl2, st);
            sh  += __shfl_xor_sync(0xffffffffu, sh,  st);
            sh2 += __shfl_xor_sync(0xffffffffu, sh2, st);
        }
        if (lane == 0) {
            g_part [bid*OUTC_ + oc0    ] = sl;
            g_part2[bid*OUTC_ + oc0    ] = sl2;
            g_part [bid*OUTC_ + oc0 + 1] = sh;
            g_part2[bid*OUTC_ + oc0 + 1] = sh2;
        }
    }
}

// ---------------------------------------------------------------------------
// Kernel 3a: reduce block partials -> mean/rstd (deterministic)
// ---------------------------------------------------------------------------
__global__ void __launch_bounds__(128) k_stats_final()
{
    const int oc = blockIdx.x;
    const int t  = threadIdx.x;
    float S = 0.f, S2 = 0.f;
    for (int i = t; i < NBLK_MAIN_; i += 128) {
        S  += g_part [i*OUTC_ + oc];
        S2 += g_part2[i*OUTC_ + oc];
    }
    __shared__ float sh[128], sh2[128];
    sh[t] = S; sh2[t] = S2;
    __syncthreads();
    for (int st = 64; st > 0; st >>= 1) {
        if (t < st) { sh[t] += sh[t + st]; sh2[t] += sh2[t + st]; }
        __syncthreads();
    }
    if (t == 0) {
        float mean = sh[0] / (float)REDN_;
        float var  = sh2[0] / (float)REDN_ - mean*mean;
        g_mean[oc] = mean;
        g_rstd[oc] = rsqrtf(var + 1e-5f);
    }
}

// ---------------------------------------------------------------------------
// Kernel 3b: BN affine + SiLU -> d_out (float4 vectorized)
// ---------------------------------------------------------------------------
__global__ void __launch_bounds__(256) k_bn_silu(
    const float* __restrict__ gamma,
    const float* __restrict__ beta,
    float* __restrict__ out)
{
    const int q = blockIdx.x * 256 + threadIdx.x;     // 1,769,472 float4s
    const int idx = q * 4;
    const int o = (idx / DHW_) & (OUTC_ - 1);         // DHW_ % 4 == 0
    const float m = g_mean[o];
    const float sg = g_rstd[o] * __ldg(&gamma[o]);
    const float bt = __ldg(&beta[o]);
    float4 v = *reinterpret_cast<const float4*>(&g_out[idx]);
    float4 r;
    {
        float y = (v.x - m) * sg + bt; r.x = y / (1.f + __expf(-y));
        y = (v.y - m) * sg + bt;       r.y = y / (1.f + __expf(-y));
        y = (v.z - m) * sg + bt;       r.z = y / (1.f + __expf(-y));
        y = (v.w - m) * sg + bt;       r.w = y / (1.f + __expf(-y));
    }
    *reinterpret_cast<float4*>(&out[idx]) = r;
}

// ---------------------------------------------------------------------------
extern "C" void kernel_launch(void* const* d_in, const int* in_sizes, int n_in,
                              void* d_out, int out_size)
{
    const float* x      = (const float*)d_in[0];
    const float* w_p    = (const float*)d_in[1];
    const float* b_p    = (const float*)d_in[2];
    const float* w_conv = (const float*)d_in[3];
    const float* gamma  = (const float*)d_in[4];
    const float* beta   = (const float*)d_in[5];
    float* out = (float*)d_out;

    cudaFuncSetAttribute(k_main, cudaFuncAttributeMaxDynamicSharedMemorySize, 98816);

    k_wt<<<INC_*NP_*OUTC_/256, 256>>>(w_conv);                 // 256 blocks
    k_xt<<<B_*DHW_/64, 256>>>(x);                              // 864 blocks
    k_offset_conv<<<576, 288>>>(x, w_p, b_p);                  // spatial-only
    k_main<<<NBLK_MAIN_, 256, 98816>>>();                      // 432 blocks
    k_stats_final<<<OUTC_, 128>>>();                           // 128 blocks
    k_bn_silu<<<B_*OUTC_*DHW_/1024, 256>>>(gamma, beta, out);  // 6912 blocks
}

// round 9
// speedup vs baseline: 1.3105x; 1.1381x over previous
#include <cuda_runtime.h>
#include <cuda_bf16.h>

// Problem constants
#define B_   2
#define INC_ 64
#define OUTC_ 128
#define NP_  8
#define D_   12
#define H_   48
#define W_   48
#define HW_   (H_*W_)        // 2304
#define DHW_  (D_*HW_)       // 27648
#define OFFC_ (3*NP_)        // 24
#define REDN_ (B_*DHW_)      // 55296
#define POSBLK_ 128
#define NBLK_MAIN_ (B_*D_*(HW_/POSBLK_))   // 432

// Scratch (device globals; no allocations allowed)
__device__ float g_offset[B_*OFFC_*DHW_];    // ~5.3 MB
__device__ float g_out[B_*OUTC_*DHW_];       // ~28.3 MB
__device__ float g_wt[INC_*NP_*OUTC_];       // w_conv -> [n][c][o]  (n-major)
__device__ float g_wp[INC_*27*OFFC_];        // w_p -> [c][k][oc]    (162 KB)
__device__ float g_xt[B_*DHW_*INC_];         // x -> channel-last [b][dhw][c]
__device__ float g_part[NBLK_MAIN_*OUTC_];
__device__ float g_part2[NBLK_MAIN_*OUTC_];
__device__ float g_mean[OUTC_];
__device__ float g_rstd[OUTC_];

// _p_n(8): base=3, dep=2, row=1, mod=2
__device__ __constant__ float c_pnz[8] = {0,0,0,1,1,1,2,2};
__device__ __constant__ float c_pnx[8] = {0,0,0,0,0,0,1,1};
__device__ __constant__ float c_pny[8] = {0,1,2,0,1,2,0,1};

// ---------------- f32x2 helpers (FFMA2 path, fp32-exact) ----------------
typedef unsigned long long u64;

__device__ __forceinline__ void ffma2(u64 &d, u64 a, u64 b) {
    asm("fma.rn.f32x2 %0, %1, %2, %0;" : "+l"(d) : "l"(a), "l"(b));
}
__device__ __forceinline__ u64 dup2(float x) {
    u64 r; asm("mov.b64 %0, {%1, %1};" : "=l"(r) : "f"(x)); return r;
}
__device__ __forceinline__ u64 pack2(float lo, float hi) {
    u64 r; asm("mov.b64 %0, {%1, %2};" : "=l"(r) : "f"(lo), "f"(hi)); return r;
}
__device__ __forceinline__ float lo32(u64 v){ return __uint_as_float((unsigned int)v); }
__device__ __forceinline__ float hi32(u64 v){ return __uint_as_float((unsigned int)(v >> 32)); }

// ---------------------------------------------------------------------------
// Kernel 0a: transpose w_conv [o][c][n] -> g_wt [n][c][o]  (n-major K order)
// ---------------------------------------------------------------------------
__global__ void k_wt(const float* __restrict__ w_conv) {
    int idx = blockIdx.x * 256 + threadIdx.x;      // 65536 total
    int nn = idx & 7;
    int c  = (idx >> 3) & 63;
    int o  = idx >> 9;
    g_wt[(nn*INC_ + c)*OUTC_ + o] = w_conv[idx];
}

// ---------------------------------------------------------------------------
// Kernel 0a': transpose w_p [oc][c][k27] -> g_wp [c][k27][oc24]
// ---------------------------------------------------------------------------
__global__ void k_wp(const float* __restrict__ w_p) {
    int idx = blockIdx.x * 256 + threadIdx.x;      // 41472 total
    if (idx >= INC_*27*OFFC_) return;
    int k  = idx % 27;
    int c  = (idx / 27) % INC_;
    int oc = idx / (27*INC_);
    g_wp[(c*27 + k)*OFFC_ + oc] = w_p[idx];
}

// ---------------------------------------------------------------------------
// Kernel 0b: transpose x [b][c][dhw] -> g_xt [b][dhw][c] (channel-last)
// ---------------------------------------------------------------------------
__global__ void __launch_bounds__(256) k_xt(const float* __restrict__ x) {
    __shared__ float tile[64][65];
    const int bid = blockIdx.x;                 // 864 blocks
    const int b = bid / (DHW_/64);
    const int p0 = (bid % (DHW_/64)) * 64;
    const int tid = threadIdx.x;
    for (int idx = tid; idx < 4096; idx += 256) {
        int c = idx >> 6, p = idx & 63;
        tile[c][p] = x[(b*INC_ + c)*DHW_ + p0 + p];
    }
    __syncthreads();
    for (int idx = tid; idx < 4096; idx += 256) {
        int p = idx >> 6, c = idx & 63;
        g_xt[(b*DHW_ + p0 + p)*INC_ + c] = tile[c][p];
    }
}

// ---------------------------------------------------------------------------
// Kernel 1: offset conv (3x3x3, pad 1), FFMA2, R4 block shape (288 blocks,
// 4 h-rows), with CHEAP staging:
//   x: strip-based -- 144 (c,dz,dh) combos x 2 halves, index math once/cc,
//      26 contiguous elements per thread with 1 predicate each.
//   w: straight float4 copy from pre-transposed g_wp.
// ---------------------------------------------------------------------------
__global__ void __launch_bounds__(288) k_offset_conv(
    const float* __restrict__ x,
    const float* __restrict__ b_p)
{
    __shared__ float x_s[8*3*6*52];     // 7488 floats: [c8][dz3][dh6][w52]
    __shared__ float w_s[8*27*24];      // 5184 floats: [c8][k27][oc24]

    const int bid = blockIdx.x;
    const int hblk = bid % (H_/4);
    const int d = (bid / (H_/4)) % D_;
    const int b = bid / ((H_/4)*D_);
    const int h0 = hblk * 4;
    const int tid = threadIdx.x;
    const int hh  = tid / 72;
    const int r   = tid % 72;
    const int ocg = r / 12;             // 0..5  (4 oc each)
    const int wq  = r % 12;             // 0..11 (4 w each)

    // staging roles (computed once)
    const int combo = tid >> 1;         // 0..143 = (c, dz, dh)
    const int halfS = tid & 1;          // 26-element half
    const int sc  = combo / 18;         // channel-in-chunk 0..7
    const int srw = combo % 18;
    const int sdz = srw / 6;            // 0..2
    const int sdh = srw % 6;            // 0..5
    const int sgd = d + sdz - 1;
    const int sgh = h0 + sdh - 1;
    const bool rowok = ((unsigned)sgd < (unsigned)D_) && ((unsigned)sgh < (unsigned)H_);
    const int srowbase = combo * 52 + halfS * 26;   // smem strip base
    const int wl0 = halfS * 26;

    u64 acc[2][4];
    {
        u64 p0 = pack2(__ldg(&b_p[ocg*4+0]), __ldg(&b_p[ocg*4+1]));
        u64 p1 = pack2(__ldg(&b_p[ocg*4+2]), __ldg(&b_p[ocg*4+3]));
        #pragma unroll
        for (int i = 0; i < 4; i++) { acc[0][i] = p0; acc[1][i] = p1; }
    }

    for (int cc = 0; cc < 8; cc++) {
        __syncthreads();
        // ---- stage x strip: 26 contiguous elements, 1 predicate each ----
        {
            const float* xrow = x + ((size_t)(b*INC_ + cc*8 + sc)*D_ + (rowok ? sgd : 0))*HW_
                                  + (rowok ? sgh : 0)*W_;
            if (rowok) {
                #pragma unroll 13
                for (int j = 0; j < 26; j++) {
                    const int gw = wl0 + j - 1;          // -1..50
                    float v = ((unsigned)gw < (unsigned)W_) ? xrow[gw] : 0.f;
                    x_s[srowbase + j] = v;
                }
            } else {
                #pragma unroll 13
                for (int j = 0; j < 26; j++) x_s[srowbase + j] = 0.f;
            }
        }
        // ---- stage weights: straight float4 copy (pre-transposed) ----
        {
            const float4* src = reinterpret_cast<const float4*>(g_wp + cc*5184);
            float4* dst = reinterpret_cast<float4*>(w_s);
            for (int i = tid; i < 1296; i += 288) dst[i] = __ldg(&src[i]);
        }
        __syncthreads();

        #pragma unroll 2
        for (int c = 0; c < 8; c++) {
            #pragma unroll
            for (int kz = 0; kz < 3; kz++)
            #pragma unroll
            for (int kx = 0; kx < 3; kx++) {
                const float* xb = &x_s[((c*3 + kz)*6 + hh + kx)*52 + wq*4];
                float4 xa = *reinterpret_cast<const float4*>(xb);
                float2 xc = *reinterpret_cast<const float2*>(xb + 4);
                u64 X[6] = { dup2(xa.x), dup2(xa.y), dup2(xa.z),
                             dup2(xa.w), dup2(xc.x), dup2(xc.y) };
                #pragma unroll
                for (int ky = 0; ky < 3; ky++) {
                    ulonglong2 Wv = *reinterpret_cast<const ulonglong2*>(
                        &w_s[(c*27 + kz*9 + kx*3 + ky)*24 + ocg*4]);
                    #pragma unroll
                    for (int i = 0; i < 4; i++) {
                        ffma2(acc[0][i], Wv.x, X[ky + i]);
                        ffma2(acc[1][i], Wv.y, X[ky + i]);
                    }
                }
            }
        }
    }

    const int h = h0 + hh;
    #pragma unroll
    for (int p = 0; p < 2; p++) {
        float4 vl = make_float4(lo32(acc[p][0]), lo32(acc[p][1]),
                                lo32(acc[p][2]), lo32(acc[p][3]));
        float4 vh = make_float4(hi32(acc[p][0]), hi32(acc[p][1]),
                                hi32(acc[p][2]), hi32(acc[p][3]));
        int oc0 = ocg*4 + p*2;
        *reinterpret_cast<float4*>(
            &g_offset[((b*OFFC_ + oc0    )*D_ + d)*HW_ + h*W_ + wq*4]) = vl;
        *reinterpret_cast<float4*>(
            &g_offset[((b*OFFC_ + oc0 + 1)*D_ + d)*HW_ + h*W_ + wq*4]) = vh;
    }
}

// ---------------------------------------------------------------------------
// Kernel 2: fused deformable gather + 1x1xN conv (FFMA2) + BN partials.
// EXACT R4 version (proven 206.8us).
// ---------------------------------------------------------------------------
__global__ void __launch_bounds__(256) k_main()
{
    extern __shared__ unsigned char smraw[];
    int*   idx_s = (int*)smraw;                          // [1024*4]
    float* gwt_s = (float*)(smraw + 16384);              // [1024*4]
    float* xoff  = (float*)(smraw + 32768);              // [128][65]
    float* wt_s  = (float*)(smraw + 32768 + 33280);      // [64][128]

    const int bid = blockIdx.x;
    const int p0   = (bid % (HW_/POSBLK_)) * POSBLK_;
    const int slab = bid / (HW_/POSBLK_);
    const int d = slab % D_;
    const int b = slab / D_;
    const int tid = threadIdx.x;
    const int lane = tid & 31;
    const int wid  = tid >> 5;

    const int bD = b * DHW_;
    #pragma unroll
    for (int i = 0; i < 4; i++) {
        const int q = tid + 256*i;          // q = n*128 + p
        const int p = q & 127;
        const int n = q >> 7;
        const int pos = p0 + p;
        const int h = pos / W_;
        const int w = pos % W_;
        const int off_base = (b*OFFC_*D_ + d)*HW_ + pos;
        const float oz = g_offset[off_base + (n       )*DHW_];
        const float ox = g_offset[off_base + (NP_  + n)*DHW_];
        const float oy = g_offset[off_base + (2*NP_+ n)*DHW_];

        const float pz = oz + (float)d + c_pnz[n];
        const float px = ox + (float)h + c_pnx[n];
        const float py = oy + (float)w + c_pny[n];

        const float fz = floorf(pz), fx = floorf(px), fy = floorf(py);
        const float z0f = fminf(fmaxf(fz,       0.f), (float)(D_-1));
        const float z1f = fminf(fmaxf(fz + 1.f, 0.f), (float)(D_-1));
        const float x0f = fminf(fmaxf(fx,       0.f), (float)(H_-1));
        const float x1f = fminf(fmaxf(fx + 1.f, 0.f), (float)(H_-1));
        const float y0f = fminf(fmaxf(fy,       0.f), (float)(W_-1));
        const float y1f = fminf(fmaxf(fy + 1.f, 0.f), (float)(W_-1));
        const float pzc = fminf(fmaxf(pz, 0.f), (float)(D_-1));
        const float pxc = fminf(fmaxf(px, 0.f), (float)(H_-1));
        const float pyc = fminf(fmaxf(py, 0.f), (float)(W_-1));

        const float az = 1.f + (z0f - pzc), bz = 1.f - (z1f - pzc);
        const float ax = 1.f + (x0f - pxc), bx = 1.f - (x1f - pxc);
        const float ay = 1.f + (y0f - pyc), by = 1.f - (y1f - pyc);

        const int z0 = (int)z0f, z1 = (int)z1f;
        const int x0 = (int)x0f, x1 = (int)x1f;
        const int y0 = (int)y0f, y1 = (int)y1f;

        idx_s[q*4+0] = (bD + z0*HW_ + x0*W_ + y0)*INC_;
        idx_s[q*4+1] = (bD + z1*HW_ + x1*W_ + y1)*INC_;
        idx_s[q*4+2] = (bD + z0*HW_ + x1*W_ + y0)*INC_;
        idx_s[q*4+3] = (bD + z1*HW_ + x0*W_ + y1)*INC_;
        gwt_s[q*4+0] = az*ax*ay;
        gwt_s[q*4+1] = bz*bx*by;
        gwt_s[q*4+2] = az*bx*ay;
        gwt_s[q*4+3] = bz*ax*by;
    }

    u64 acc[8][4];
    #pragma unroll
    for (int pr = 0; pr < 8; pr++)
        #pragma unroll
        for (int j = 0; j < 4; j++) acc[pr][j] = 0ull;

    const int f    = lane & 15;     // channel-quad
    const int half = lane >> 4;     // corner pair selector

    for (int nn = 0; nn < 8; nn++) {
        __syncthreads();
        {
            const float4* src = reinterpret_cast<const float4*>(g_wt + nn*8192);
            float4* dst = reinterpret_cast<float4*>(wt_s);
            #pragma unroll
            for (int j = 0; j < 8; j++) dst[tid + 256*j] = __ldg(&src[tid + 256*j]);
        }
        #pragma unroll 2
        for (int pp = 0; pp < 16; pp++) {
            const int p = wid*16 + pp;
            const int q4 = ((nn << 7) + p) << 2;
            const int   i0 = idx_s[q4 + half];
            const float g0 = gwt_s[q4 + half];
            const int   i1 = idx_s[q4 + half + 2];
            const float g1 = gwt_s[q4 + half + 2];
            const float4 v0 = __ldg((const float4*)(g_xt + i0 + 4*f));
            const float4 v1 = __ldg((const float4*)(g_xt + i1 + 4*f));
            float4 rv;
            rv.x = g0*v0.x + g1*v1.x;
            rv.y = g0*v0.y + g1*v1.y;
            rv.z = g0*v0.z + g1*v1.z;
            rv.w = g0*v0.w + g1*v1.w;
            rv.x += __shfl_xor_sync(0xffffffffu, rv.x, 16);
            rv.y += __shfl_xor_sync(0xffffffffu, rv.y, 16);
            rv.z += __shfl_xor_sync(0xffffffffu, rv.z, 16);
            rv.w += __shfl_xor_sync(0xffffffffu, rv.w, 16);
            if (half == 0) {
                float* rowp = &xoff[p*65 + 4*f];
                rowp[0] = rv.x;
                rowp[1] = rv.y;
                rowp[2] = rv.z;
                rowp[3] = rv.w;
            }
        }
        __syncthreads();

        const int ocg = wid;
        #pragma unroll 4
        for (int k = 0; k < 64; k++) {
            const float x0 = xoff[(lane      )*65 + k];
            const float x1 = xoff[(lane + 32 )*65 + k];
            const float x2 = xoff[(lane + 64 )*65 + k];
            const float x3 = xoff[(lane + 96 )*65 + k];
            const ulonglong2 wa = *reinterpret_cast<const ulonglong2*>(&wt_s[k*128 + ocg*16     ]);
            const ulonglong2 wb = *reinterpret_cast<const ulonglong2*>(&wt_s[k*128 + ocg*16 + 4 ]);
            const ulonglong2 wc = *reinterpret_cast<const ulonglong2*>(&wt_s[k*128 + ocg*16 + 8 ]);
            const ulonglong2 wd = *reinterpret_cast<const ulonglong2*>(&wt_s[k*128 + ocg*16 + 12]);
            const u64 X0 = dup2(x0), X1 = dup2(x1), X2 = dup2(x2), X3 = dup2(x3);
            ffma2(acc[0][0], wa.x, X0); ffma2(acc[0][1], wa.x, X1);
            ffma2(acc[0][2], wa.x, X2); ffma2(acc[0][3], wa.x, X3);
            ffma2(acc[1][0], wa.y, X0); ffma2(acc[1][1], wa.y, X1);
            ffma2(acc[1][2], wa.y, X2); ffma2(acc[1][3], wa.y, X3);
            ffma2(acc[2][0], wb.x, X0); ffma2(acc[2][1], wb.x, X1);
            ffma2(acc[2][2], wb.x, X2); ffma2(acc[2][3], wb.x, X3);
            ffma2(acc[3][0], wb.y, X0); ffma2(acc[3][1], wb.y, X1);
            ffma2(acc[3][2], wb.y, X2); ffma2(acc[3][3], wb.y, X3);
            ffma2(acc[4][0], wc.x, X0); ffma2(acc[4][1], wc.x, X1);
            ffma2(acc[4][2], wc.x, X2); ffma2(acc[4][3], wc.x, X3);
            ffma2(acc[5][0], wc.y, X0); ffma2(acc[5][1], wc.y, X1);
            ffma2(acc[5][2], wc.y, X2); ffma2(acc[5][3], wc.y, X3);
            ffma2(acc[6][0], wd.x, X0); ffma2(acc[6][1], wd.x, X1);
            ffma2(acc[6][2], wd.x, X2); ffma2(acc[6][3], wd.x, X3);
            ffma2(acc[7][0], wd.y, X0); ffma2(acc[7][1], wd.y, X1);
            ffma2(acc[7][2], wd.y, X2); ffma2(acc[7][3], wd.y, X3);
        }
    }

    const int ocg = wid;
    #pragma unroll
    for (int pr = 0; pr < 8; pr++) {
        const int oc0 = ocg*16 + pr*2;
        float sl = 0.f, sl2 = 0.f, sh = 0.f, sh2 = 0.f;
        #pragma unroll
        for (int j = 0; j < 4; j++) {
            const int pos = p0 + lane + 32*j;
            const float vl = lo32(acc[pr][j]);
            const float vh = hi32(acc[pr][j]);
            g_out[((b*OUTC_ + oc0    )*D_ + d)*HW_ + pos] = vl;
            g_out[((b*OUTC_ + oc0 + 1)*D_ + d)*HW_ + pos] = vh;
            sl += vl; sl2 += vl*vl;
            sh += vh; sh2 += vh*vh;
        }
        #pragma unroll
        for (int st = 16; st > 0; st >>= 1) {
            sl  += __shfl_xor_sync(0xffffffffu, sl,  st);
            sl2 += __shfl_xor_sync(0xffffffffu, sl2, st);
            sh  += __shfl_xor_sync(0xffffffffu, sh,  st);
            sh2 += __shfl_xor_sync(0xffffffffu, sh2, st);
        }
        if (lane == 0) {
            g_part [bid*OUTC_ + oc0    ] = sl;
            g_part2[bid*OUTC_ + oc0    ] = sl2;
            g_part [bid*OUTC_ + oc0 + 1] = sh;
            g_part2[bid*OUTC_ + oc0 + 1] = sh2;
        }
    }
}

// ---------------------------------------------------------------------------
// Kernel 3a: reduce block partials -> mean/rstd (deterministic)
// ---------------------------------------------------------------------------
__global__ void __launch_bounds__(128) k_stats_final()
{
    const int oc = blockIdx.x;
    const int t  = threadIdx.x;
    float S = 0.f, S2 = 0.f;
    for (int i = t; i < NBLK_MAIN_; i += 128) {
        S  += g_part [i*OUTC_ + oc];
        S2 += g_part2[i*OUTC_ + oc];
    }
    __shared__ float sh[128], sh2[128];
    sh[t] = S; sh2[t] = S2;
    __syncthreads();
    for (int st = 64; st > 0; st >>= 1) {
        if (t < st) { sh[t] += sh[t + st]; sh2[t] += sh2[t + st]; }
        __syncthreads();
    }
    if (t == 0) {
        float mean = sh[0] / (float)REDN_;
        float var  = sh2[0] / (float)REDN_ - mean*mean;
        g_mean[oc] = mean;
        g_rstd[oc] = rsqrtf(var + 1e-5f);
    }
}

// ---------------------------------------------------------------------------
// Kernel 3b: BN affine + SiLU -> d_out (float4 vectorized)
// ---------------------------------------------------------------------------
__global__ void __launch_bounds__(256) k_bn_silu(
    const float* __restrict__ gamma,
    const float* __restrict__ beta,
    float* __restrict__ out)
{
    const int q = blockIdx.x * 256 + threadIdx.x;     // 1,769,472 float4s
    const int idx = q * 4;
    const int o = (idx / DHW_) & (OUTC_ - 1);         // DHW_ % 4 == 0
    const float m = g_mean[o];
    const float sg = g_rstd[o] * __ldg(&gamma[o]);
    const float bt = __ldg(&beta[o]);
    float4 v = *reinterpret_cast<const float4*>(&g_out[idx]);
    float4 r;
    {
        float y = (v.x - m) * sg + bt; r.x = y / (1.f + __expf(-y));
        y = (v.y - m) * sg + bt;       r.y = y / (1.f + __expf(-y));
        y = (v.z - m) * sg + bt;       r.z = y / (1.f + __expf(-y));
        y = (v.w - m) * sg + bt;       r.w = y / (1.f + __expf(-y));
    }
    *reinterpret_cast<float4*>(&out[idx]) = r;
}

// ---------------------------------------------------------------------------
extern "C" void kernel_launch(void* const* d_in, const int* in_sizes, int n_in,
                              void* d_out, int out_size)
{
    const float* x      = (const float*)d_in[0];
    const float* w_p    = (const float*)d_in[1];
    const float* b_p    = (const float*)d_in[2];
    const float* w_conv = (const float*)d_in[3];
    const float* gamma  = (const float*)d_in[4];
    const float* beta   = (const float*)d_in[5];
    float* out = (float*)d_out;

    cudaFuncSetAttribute(k_main, cudaFuncAttributeMaxDynamicSharedMemorySize, 98816);

    k_wt<<<INC_*NP_*OUTC_/256, 256>>>(w_conv);                 // 256 blocks
    k_wp<<<(INC_*27*OFFC_ + 255)/256, 256>>>(w_p);             // 162 blocks
    k_xt<<<B_*DHW_/64, 256>>>(x);                              // 864 blocks
    k_offset_conv<<<B_*D_*(H_/4), 288>>>(x, b_p);              // 288 blocks
    k_main<<<NBLK_MAIN_, 256, 98816>>>();                      // 432 blocks
    k_stats_final<<<OUTC_, 128>>>();                           // 128 blocks
    k_bn_silu<<<B_*OUTC_*DHW_/1024, 256>>>(gamma, beta, out);  // 6912 blocks
}